// round 5
// baseline (speedup 1.0000x reference)
#include <cuda_runtime.h>
#include <cstdint>
#include <math.h>

// Problem constants: x[2,2048,1024], 16 heads, head dim 64.
#define BDIM   2
#define TSEQ   2048
#define CDIM   1024
#define NHEAD  16
#define HDIM   64
#define MROWS  (BDIM * TSEQ)   // 4096
#define QKVLD  (3 * CDIM)      // 3072

// Scratch (allocation-free rule: __device__ globals).
__device__ float g_qkv[(size_t)MROWS * QKVLD];  // [4096, 3072] fp32
__device__ float g_att[(size_t)MROWS * CDIM];   // [4096, 1024] fp32

// ---------------------------------------------------------------------------
// tf32 helpers
// ---------------------------------------------------------------------------
__device__ __forceinline__ uint32_t f2tf(float x) {
    uint32_t r;
    asm("cvt.rna.tf32.f32 %0, %1;" : "=r"(r) : "f"(x));
    return r;
}
__device__ __forceinline__ float f2tff(float x) { return __uint_as_float(f2tf(x)); }

// D += A(16x8, row) * B(8x8, col), tf32 inputs / fp32 accum.
__device__ __forceinline__ void mma8(float d[4],
        uint32_t a0, uint32_t a1, uint32_t a2, uint32_t a3,
        uint32_t b0, uint32_t b1) {
    asm volatile(
        "mma.sync.aligned.m16n8k8.row.col.f32.tf32.tf32.f32 "
        "{%0,%1,%2,%3}, {%4,%5,%6,%7}, {%8,%9}, {%0,%1,%2,%3};\n"
        : "+f"(d[0]), "+f"(d[1]), "+f"(d[2]), "+f"(d[3])
        : "r"(a0), "r"(a1), "r"(a2), "r"(a3), "r"(b0), "r"(b1));
}

// ---------------------------------------------------------------------------
// GEMM: C[M,N] = A[M,K] @ W[N,K]^T + bias[N]   (both operands K-major)
// Tile 128x128x32, 256 threads (2x4 warps, 64x32 per warp).
// M,N,K are multiples of 128/128/32 for all call sites (no bounds checks).
// ---------------------------------------------------------------------------
#define BM 128
#define BN 128
#define BK 32
#define GPAD 36   // row pad (floats): frag LDS bank = 4*group + tg -> conflict-free

__global__ __launch_bounds__(256)
void gemm_tf32(const float* __restrict__ A, const float* __restrict__ W,
               const float* __restrict__ bias, float* __restrict__ C,
               int M, int N, int K) {
    __shared__ float As[BM][GPAD];
    __shared__ float Bs[BN][GPAD];

    const int tid  = threadIdx.x;
    const int warp = tid >> 5;
    const int lane = tid & 31;
    const int g    = lane >> 2;   // groupID 0..7
    const int t    = lane & 3;    // threadID_in_group 0..3
    const int wm   = warp >> 2;   // 0..1
    const int wn   = warp & 3;    // 0..3
    const int m0   = blockIdx.y * BM;
    const int n0   = blockIdx.x * BN;

    float acc[4][4][4];
    #pragma unroll
    for (int mi = 0; mi < 4; mi++)
        #pragma unroll
        for (int ni = 0; ni < 4; ni++)
            #pragma unroll
            for (int r = 0; r < 4; r++) acc[mi][ni][r] = 0.f;

    for (int k0 = 0; k0 < K; k0 += BK) {
        // Load A tile (128x32) and W tile (128x32), tf32-round at store.
        #pragma unroll
        for (int i = 0; i < 4; i++) {
            int idx = tid + i * 256;          // 0..1023 float4 slots
            int r   = idx >> 3;               // 8 float4 per 32-float row
            int c   = (idx & 7) << 2;
            float4 va = *(const float4*)&A[(size_t)(m0 + r) * K + k0 + c];
            As[r][c + 0] = f2tff(va.x);
            As[r][c + 1] = f2tff(va.y);
            As[r][c + 2] = f2tff(va.z);
            As[r][c + 3] = f2tff(va.w);
            float4 vw = *(const float4*)&W[(size_t)(n0 + r) * K + k0 + c];
            Bs[r][c + 0] = f2tff(vw.x);
            Bs[r][c + 1] = f2tff(vw.y);
            Bs[r][c + 2] = f2tff(vw.z);
            Bs[r][c + 3] = f2tff(vw.w);
        }
        __syncthreads();

        #pragma unroll
        for (int kk = 0; kk < BK; kk += 8) {
            uint32_t af[4][4], bf[4][2];
            #pragma unroll
            for (int mi = 0; mi < 4; mi++) {
                int r = wm * 64 + mi * 16 + g;
                int c = kk + t;
                af[mi][0] = __float_as_uint(As[r    ][c    ]);
                af[mi][1] = __float_as_uint(As[r + 8][c    ]);
                af[mi][2] = __float_as_uint(As[r    ][c + 4]);
                af[mi][3] = __float_as_uint(As[r + 8][c + 4]);
            }
            #pragma unroll
            for (int ni = 0; ni < 4; ni++) {
                int n = wn * 32 + ni * 8 + g;
                bf[ni][0] = __float_as_uint(Bs[n][kk + t    ]);
                bf[ni][1] = __float_as_uint(Bs[n][kk + t + 4]);
            }
            #pragma unroll
            for (int mi = 0; mi < 4; mi++)
                #pragma unroll
                for (int ni = 0; ni < 4; ni++)
                    mma8(acc[mi][ni], af[mi][0], af[mi][1], af[mi][2], af[mi][3],
                         bf[ni][0], bf[ni][1]);
        }
        __syncthreads();
    }

    // Epilogue: + bias, fp32 out.
    #pragma unroll
    for (int mi = 0; mi < 4; mi++) {
        int r = m0 + wm * 64 + mi * 16 + g;
        #pragma unroll
        for (int ni = 0; ni < 4; ni++) {
            int c = n0 + wn * 32 + ni * 8 + t * 2;
            float b0 = bias[c], b1 = bias[c + 1];
            C[(size_t)r * N + c]           = acc[mi][ni][0] + b0;
            C[(size_t)r * N + c + 1]       = acc[mi][ni][1] + b1;
            C[(size_t)(r + 8) * N + c]     = acc[mi][ni][2] + b0;
            C[(size_t)(r + 8) * N + c + 1] = acc[mi][ni][3] + b1;
        }
    }
}

// ---------------------------------------------------------------------------
// Flash attention (causal), fp32 softmax, tf32 MMAs.
// Grid: (T/64 q-tiles, B*H). Block: 128 threads (4 warps x 16 query rows).
// Dynamic smem: Qs/Ks/Vs/Ps, 64 x 68 floats each = 69632 B.
// ---------------------------------------------------------------------------
#define AP 68
#define NEG_INF __int_as_float(0xff800000)

__global__ __launch_bounds__(128)
void flash_attn(const float* __restrict__ qkv, float* __restrict__ out) {
    extern __shared__ float sm[];
    float* Qs = sm;
    float* Ks = sm + 64 * AP;
    float* Vs = sm + 2 * 64 * AP;
    float* Ps = sm + 3 * 64 * AP;

    const int tid  = threadIdx.x;
    const int warp = tid >> 5;
    const int lane = tid & 31;
    const int g    = lane >> 2;
    const int t    = lane & 3;
    const int qt   = blockIdx.x;          // query tile 0..31
    const int bh   = blockIdx.y;          // 0..31
    const int b    = bh >> 4;
    const int h    = bh & 15;
    const int t0   = qt * 64;

    const size_t rowbase = (size_t)(b * TSEQ) * QKVLD;
    const int qoff = h * HDIM;
    const int koff = CDIM + h * HDIM;
    const int voff = 2 * CDIM + h * HDIM;

    // Load Q tile [64 x 64] (tf32-rounded).
    #pragma unroll
    for (int i = 0; i < 8; i++) {
        int idx = tid + i * 128;          // 1024 float4 slots
        int r = idx >> 4;
        int c = (idx & 15) << 2;
        float4 v = *(const float4*)&qkv[rowbase + (size_t)(t0 + r) * QKVLD + qoff + c];
        Qs[r * AP + c + 0] = f2tff(v.x);
        Qs[r * AP + c + 1] = f2tff(v.y);
        Qs[r * AP + c + 2] = f2tff(v.z);
        Qs[r * AP + c + 3] = f2tff(v.w);
    }

    float o[8][4];
    #pragma unroll
    for (int ni = 0; ni < 8; ni++)
        #pragma unroll
        for (int r = 0; r < 4; r++) o[ni][r] = 0.f;
    float m0r = NEG_INF, m1r = NEG_INF;   // running max, rows g / g+8
    float l0 = 0.f, l1 = 0.f;             // running denom
    const float scale = 0.125f;           // 1/sqrt(64)

    const int row0 = t0 + warp * 16 + g;
    const int row1 = row0 + 8;

    for (int j = 0; j <= qt; j++) {
        __syncthreads();                  // prior PV reads of Vs done
        // Load K/V tile j [64 x 64].
        #pragma unroll
        for (int i = 0; i < 8; i++) {
            int idx = tid + i * 128;
            int r = idx >> 4;
            int c = (idx & 15) << 2;
            size_t rb = rowbase + (size_t)(j * 64 + r) * QKVLD;
            float4 kv = *(const float4*)&qkv[rb + koff + c];
            Ks[r * AP + c + 0] = f2tff(kv.x);
            Ks[r * AP + c + 1] = f2tff(kv.y);
            Ks[r * AP + c + 2] = f2tff(kv.z);
            Ks[r * AP + c + 3] = f2tff(kv.w);
            float4 vv = *(const float4*)&qkv[rb + voff + c];
            Vs[r * AP + c + 0] = f2tff(vv.x);
            Vs[r * AP + c + 1] = f2tff(vv.y);
            Vs[r * AP + c + 2] = f2tff(vv.z);
            Vs[r * AP + c + 3] = f2tff(vv.w);
        }
        __syncthreads();

        // S = Q @ K^T  (per warp: 16 x 64)
        float s[8][4];
        #pragma unroll
        for (int ni = 0; ni < 8; ni++)
            #pragma unroll
            for (int r = 0; r < 4; r++) s[ni][r] = 0.f;
        #pragma unroll
        for (int kk = 0; kk < 64; kk += 8) {
            int qr = (warp * 16 + g) * AP + kk + t;
            uint32_t a0 = __float_as_uint(Qs[qr]);
            uint32_t a1 = __float_as_uint(Qs[qr + 8 * AP]);
            uint32_t a2 = __float_as_uint(Qs[qr + 4]);
            uint32_t a3 = __float_as_uint(Qs[qr + 8 * AP + 4]);
            #pragma unroll
            for (int ni = 0; ni < 8; ni++) {
                int kr = (ni * 8 + g) * AP + kk + t;
                mma8(s[ni], a0, a1, a2, a3,
                     __float_as_uint(Ks[kr]), __float_as_uint(Ks[kr + 4]));
            }
        }

        // Scale + causal mask (diagonal tile only).
        #pragma unroll
        for (int ni = 0; ni < 8; ni++) {
            #pragma unroll
            for (int r = 0; r < 4; r++) s[ni][r] *= scale;
            if (j == qt) {
                int c0 = j * 64 + ni * 8 + t * 2;
                if (c0     > row0) s[ni][0] = NEG_INF;
                if (c0 + 1 > row0) s[ni][1] = NEG_INF;
                if (c0     > row1) s[ni][2] = NEG_INF;
                if (c0 + 1 > row1) s[ni][3] = NEG_INF;
            }
        }

        // Row max (within thread, then across the 4-lane quad).
        float rm0 = NEG_INF, rm1 = NEG_INF;
        #pragma unroll
        for (int ni = 0; ni < 8; ni++) {
            rm0 = fmaxf(rm0, fmaxf(s[ni][0], s[ni][1]));
            rm1 = fmaxf(rm1, fmaxf(s[ni][2], s[ni][3]));
        }
        rm0 = fmaxf(rm0, __shfl_xor_sync(0xffffffffu, rm0, 1));
        rm0 = fmaxf(rm0, __shfl_xor_sync(0xffffffffu, rm0, 2));
        rm1 = fmaxf(rm1, __shfl_xor_sync(0xffffffffu, rm1, 1));
        rm1 = fmaxf(rm1, __shfl_xor_sync(0xffffffffu, rm1, 2));

        float mn0 = fmaxf(m0r, rm0);
        float mn1 = fmaxf(m1r, rm1);
        float al0 = __expf(m0r - mn0);
        float al1 = __expf(m1r - mn1);
        m0r = mn0; m1r = mn1;

        // P = exp(S - m), store tf32-rounded to Ps; row sums.
        float ps0 = 0.f, ps1 = 0.f;
        int pr = (warp * 16 + g) * AP;
        #pragma unroll
        for (int ni = 0; ni < 8; ni++) {
            int lc = ni * 8 + t * 2;
            float p0 = __expf(s[ni][0] - mn0);
            float p1 = __expf(s[ni][1] - mn0);
            float p2 = __expf(s[ni][2] - mn1);
            float p3 = __expf(s[ni][3] - mn1);
            ps0 += p0 + p1;
            ps1 += p2 + p3;
            Ps[pr + lc]              = f2tff(p0);
            Ps[pr + lc + 1]          = f2tff(p1);
            Ps[pr + 8 * AP + lc]     = f2tff(p2);
            Ps[pr + 8 * AP + lc + 1] = f2tff(p3);
        }
        ps0 += __shfl_xor_sync(0xffffffffu, ps0, 1);
        ps0 += __shfl_xor_sync(0xffffffffu, ps0, 2);
        ps1 += __shfl_xor_sync(0xffffffffu, ps1, 1);
        ps1 += __shfl_xor_sync(0xffffffffu, ps1, 2);
        l0 = l0 * al0 + ps0;
        l1 = l1 * al1 + ps1;

        // Rescale running output.
        #pragma unroll
        for (int ni = 0; ni < 8; ni++) {
            o[ni][0] *= al0; o[ni][1] *= al0;
            o[ni][2] *= al1; o[ni][3] *= al1;
        }
        __syncwarp();   // Ps is per-warp private; warp-local write->read fence

        // O += P @ V  (per warp: 16 x 64)
        #pragma unroll
        for (int kk = 0; kk < 64; kk += 8) {
            int ar = (warp * 16 + g) * AP + kk + t;
            uint32_t a0 = __float_as_uint(Ps[ar]);
            uint32_t a1 = __float_as_uint(Ps[ar + 8 * AP]);
            uint32_t a2 = __float_as_uint(Ps[ar + 4]);
            uint32_t a3 = __float_as_uint(Ps[ar + 8 * AP + 4]);
            #pragma unroll
            for (int ni = 0; ni < 8; ni++) {
                int vr = (kk + t) * AP + ni * 8 + g;
                mma8(o[ni], a0, a1, a2, a3,
                     __float_as_uint(Vs[vr]), __float_as_uint(Vs[vr + 4 * AP]));
            }
        }
    }

    // Normalize and write out (head-interleaved [B*T, C]).
    float inv0 = 1.f / l0, inv1 = 1.f / l1;
    size_t ob = (size_t)(b * TSEQ + t0 + warp * 16) * CDIM + h * HDIM;
    #pragma unroll
    for (int ni = 0; ni < 8; ni++) {
        int c = ni * 8 + t * 2;
        out[ob + (size_t)g * CDIM + c]           = o[ni][0] * inv0;
        out[ob + (size_t)g * CDIM + c + 1]       = o[ni][1] * inv0;
        out[ob + (size_t)(g + 8) * CDIM + c]     = o[ni][2] * inv1;
        out[ob + (size_t)(g + 8) * CDIM + c + 1] = o[ni][3] * inv1;
    }
}

// ---------------------------------------------------------------------------
// Launch
// ---------------------------------------------------------------------------
extern "C" void kernel_launch(void* const* d_in, const int* in_sizes, int n_in,
                              void* d_out, int out_size) {
    (void)in_sizes; (void)n_in; (void)out_size;
    const float* x      = (const float*)d_in[0];
    const float* attn_w = (const float*)d_in[1];
    const float* attn_b = (const float*)d_in[2];
    const float* proj_w = (const float*)d_in[3];
    const float* proj_b = (const float*)d_in[4];
    float* out = (float*)d_out;

    float *qkv, *att;
    cudaGetSymbolAddress((void**)&qkv, g_qkv);
    cudaGetSymbolAddress((void**)&att, g_att);

    // 1) QKV projection: [4096,1024] @ [3072,1024]^T + b
    gemm_tf32<<<dim3(QKVLD / BN, MROWS / BM), 256>>>(
        x, attn_w, attn_b, qkv, MROWS, QKVLD, CDIM);

    // 2) Causal flash attention -> g_att
    const int smem = 4 * 64 * AP * sizeof(float);   // 69632 B
    cudaFuncSetAttribute(flash_attn, cudaFuncAttributeMaxDynamicSharedMemorySize, smem);
    flash_attn<<<dim3(TSEQ / 64, BDIM * NHEAD), 128, smem>>>(qkv, att);

    // 3) Output projection: [4096,1024] @ [1024,1024]^T + b -> d_out
    gemm_tf32<<<dim3(CDIM / BN, MROWS / BM), 256>>>(
        att, proj_w, proj_b, out, MROWS, CDIM, CDIM);
}